// round 2
// baseline (speedup 1.0000x reference)
#include <cuda_runtime.h>

#define DIM    256
#define NQ     8
#define FFN    2048
#define EMBED  512
#define BS     32768            // B * S = 4 * 8192
#define OUT_F4 (BS * EMBED / 4) // 4,194,304 float4

// Scratch (device globals — allocation-free per harness rules)
__device__ float g_h[FFN];
__device__ float g_o[EMBED];

// ---------------------------------------------------------------------------
// K1: z from U's first column, then h = relu(W1 @ z + b1). One block, 512 thr.
// ---------------------------------------------------------------------------
__global__ void k_quantum_h(const float* __restrict__ U_re,
                            const float* __restrict__ U_im,
                            const float* __restrict__ W1,
                            const float* __restrict__ b1)
{
    __shared__ float sp[DIM];
    __shared__ float sz[NQ];
    const int t = threadIdx.x;

    // probs of |psi> = U[:,0]  (row stride DIM)
    if (t < DIM) {
        float re = U_re[t * DIM];
        float im = U_im[t * DIM];
        sp[t] = re * re + im * im;
    }
    __syncthreads();

    // z[i] = sum_s p[s] * (1 - 2*bit_{7-i}(s))   (axis 0 of (2,)*8 is the MSB)
    if (t < NQ) {
        const int bit = (NQ - 1) - t;
        float acc = 0.f;
        for (int s = 0; s < DIM; ++s)
            acc += ((s >> bit) & 1) ? -sp[s] : sp[s];
        sz[t] = acc;
    }
    __syncthreads();

    // h[f] = relu(b1[f] + sum_q z[q] * W1[f][q]);  W1 is (FFN, 8) row-major
    for (int f = t; f < FFN; f += blockDim.x) {
        float acc = b1[f];
        const float4 w0 = __ldg((const float4*)(W1 + f * NQ));
        const float4 w1 = __ldg((const float4*)(W1 + f * NQ + 4));
        acc += sz[0]*w0.x + sz[1]*w0.y + sz[2]*w0.z + sz[3]*w0.w;
        acc += sz[4]*w1.x + sz[5]*w1.y + sz[6]*w1.z + sz[7]*w1.w;
        g_h[f] = fmaxf(acc, 0.f);
    }
}

// ---------------------------------------------------------------------------
// K2: o[e] = b2[e] + dot(h, W2[e,:]).  One block per e, 256 threads.
// ---------------------------------------------------------------------------
__global__ void k_gemv_o(const float* __restrict__ W2,
                         const float* __restrict__ b2)
{
    const int e = blockIdx.x;
    const int t = threadIdx.x;

    const float4* __restrict__ w4 = (const float4*)(W2 + (size_t)e * FFN);
    const float4* __restrict__ h4 = (const float4*)g_h;

    float acc = 0.f;
    #pragma unroll
    for (int i = t; i < FFN / 4; i += 256) {
        float4 w = __ldg(&w4[i]);
        float4 h = h4[i];
        acc += w.x*h.x + w.y*h.y + w.z*h.z + w.w*h.w;
    }

    // warp reduce
    #pragma unroll
    for (int off = 16; off > 0; off >>= 1)
        acc += __shfl_xor_sync(0xFFFFFFFFu, acc, off);

    __shared__ float swarp[8];
    if ((t & 31) == 0) swarp[t >> 5] = acc;
    __syncthreads();

    if (t == 0) {
        float s = 0.f;
        #pragma unroll
        for (int w = 0; w < 8; ++w) s += swarp[w];
        g_o[e] = s + b2[e];
    }
}

// ---------------------------------------------------------------------------
// K3: broadcast o[512] into out (BS rows). Pure STG.128 streaming.
//     Row = 512 floats = 128 float4, so float4-slot index & 127 selects column.
// ---------------------------------------------------------------------------
__global__ void k_broadcast(float4* __restrict__ out)
{
    __shared__ float4 so[EMBED / 4];
    if (threadIdx.x < EMBED / 4)
        so[threadIdx.x] = ((const float4*)g_o)[threadIdx.x];
    __syncthreads();

    unsigned idx    = blockIdx.x * blockDim.x + threadIdx.x;
    unsigned stride = gridDim.x * blockDim.x;
    for (; idx < OUT_F4; idx += stride)
        out[idx] = so[idx & (EMBED / 4 - 1)];
}

// ---------------------------------------------------------------------------
extern "C" void kernel_launch(void* const* d_in, const int* in_sizes, int n_in,
                              void* d_out, int out_size)
{
    // metadata order: x, U_re, U_im, W1, b1, W2, b2  (x unused by the math)
    const float* U_re = (const float*)d_in[1];
    const float* U_im = (const float*)d_in[2];
    const float* W1   = (const float*)d_in[3];
    const float* b1   = (const float*)d_in[4];
    const float* W2   = (const float*)d_in[5];
    const float* b2   = (const float*)d_in[6];
    float*       out  = (float*)d_out;

    k_quantum_h<<<1, 512>>>(U_re, U_im, W1, b1);
    k_gemv_o<<<EMBED, 256>>>(W2, b2);
    // 148 SMs * 8 blocks -> full-chip store saturation, grid-stride ~14 iters
    k_broadcast<<<1184, 256>>>((float4*)out);
}

// round 3
// speedup vs baseline: 1.1218x; 1.1218x over previous
#include <cuda_runtime.h>

#define DIM    256
#define NQ     8
#define FFN    2048
#define EMBED  512
#define BS     32768            // B * S = 4 * 8192
#define OUT_F4 (BS * EMBED / 4) // 4,194,304 float4

#define K1_BLOCKS 8             // 8 blocks x 256 rows of h each

// Scratch (device globals — allocation-free per harness rules)
__device__ float g_h[FFN];
__device__ float g_o[EMBED];

// ---------------------------------------------------------------------------
// K1: each block redundantly computes z (parallel shuffle reduction), then
//     its 256-row slice of h = relu(W1 @ z + b1). 8 blocks x 256 threads.
// ---------------------------------------------------------------------------
__global__ void k_quantum_h(const float* __restrict__ U_re,
                            const float* __restrict__ U_im,
                            const float* __restrict__ W1,
                            const float* __restrict__ b1)
{
    const int t    = threadIdx.x;      // 0..255
    const int lane = t & 31;
    const int warp = t >> 5;           // 0..7

    // thread t owns amplitude t of |psi> = U[:,0] (row stride DIM)
    float re = U_re[t * DIM];
    float im = U_im[t * DIM];
    float p  = re * re + im * im;

    // z[q] = sum_s sign(s,q) * p[s], sign flips on bit (7-q) of s.
    __shared__ float part[NQ][NQ];     // [warp][qubit]
    #pragma unroll
    for (int q = 0; q < NQ; ++q) {
        const int bit = (NQ - 1) - q;
        float v = ((t >> bit) & 1) ? -p : p;
        #pragma unroll
        for (int off = 16; off > 0; off >>= 1)
            v += __shfl_xor_sync(0xFFFFFFFFu, v, off);
        if (lane == 0) part[warp][q] = v;
    }
    __syncthreads();

    __shared__ float sz[NQ];
    if (t < NQ) {
        float s = 0.f;
        #pragma unroll
        for (int w = 0; w < NQ; ++w) s += part[w][t];
        sz[t] = s;
    }
    __syncthreads();

    // h row f = base + t  (one row per thread; W1 is (FFN, 8) row-major)
    const int f = blockIdx.x * 256 + t;
    float acc = b1[f];
    const float4 w0 = __ldg((const float4*)(W1 + f * NQ));
    const float4 w1 = __ldg((const float4*)(W1 + f * NQ + 4));
    acc += sz[0]*w0.x + sz[1]*w0.y + sz[2]*w0.z + sz[3]*w0.w;
    acc += sz[4]*w1.x + sz[5]*w1.y + sz[6]*w1.z + sz[7]*w1.w;
    g_h[f] = fmaxf(acc, 0.f);
}

// ---------------------------------------------------------------------------
// K2: o[e] = b2[e] + dot(h, W2[e,:]).  One block per e, 256 threads.
// ---------------------------------------------------------------------------
__global__ void k_gemv_o(const float* __restrict__ W2,
                         const float* __restrict__ b2)
{
    const int e = blockIdx.x;
    const int t = threadIdx.x;

    const float4* __restrict__ w4 = (const float4*)(W2 + (size_t)e * FFN);
    const float4* __restrict__ h4 = (const float4*)g_h;

    float acc = 0.f;
    #pragma unroll
    for (int i = t; i < FFN / 4; i += 256) {
        float4 w = __ldg(&w4[i]);
        float4 h = h4[i];
        acc += w.x*h.x + w.y*h.y + w.z*h.z + w.w*h.w;
    }

    #pragma unroll
    for (int off = 16; off > 0; off >>= 1)
        acc += __shfl_xor_sync(0xFFFFFFFFu, acc, off);

    __shared__ float swarp[8];
    if ((t & 31) == 0) swarp[t >> 5] = acc;
    __syncthreads();

    if (t == 0) {
        float s = 0.f;
        #pragma unroll
        for (int w = 0; w < 8; ++w) s += swarp[w];
        g_o[e] = s + b2[e];
    }
}

// ---------------------------------------------------------------------------
// K3: broadcast o[512] into out (BS rows). Pure STG.128 streaming.
//     stride is a multiple of 128 f4-slots, so each thread's column index
//     (idx & 127) is loop-invariant -> hoist the value into a register.
// ---------------------------------------------------------------------------
__global__ void k_broadcast(float4* __restrict__ out)
{
    __shared__ float4 so[EMBED / 4];
    if (threadIdx.x < EMBED / 4)
        so[threadIdx.x] = ((const float4*)g_o)[threadIdx.x];
    __syncthreads();

    unsigned idx    = blockIdx.x * blockDim.x + threadIdx.x;
    const unsigned stride = gridDim.x * blockDim.x;   // multiple of 128
    const float4 v = so[idx & (EMBED / 4 - 1)];

    for (; idx < OUT_F4; idx += stride)
        out[idx] = v;
}

// ---------------------------------------------------------------------------
extern "C" void kernel_launch(void* const* d_in, const int* in_sizes, int n_in,
                              void* d_out, int out_size)
{
    // metadata order: x, U_re, U_im, W1, b1, W2, b2  (x unused by the math)
    const float* U_re = (const float*)d_in[1];
    const float* U_im = (const float*)d_in[2];
    const float* W1   = (const float*)d_in[3];
    const float* b1   = (const float*)d_in[4];
    const float* W2   = (const float*)d_in[5];
    const float* b2   = (const float*)d_in[6];
    float*       out  = (float*)d_out;

    k_quantum_h<<<K1_BLOCKS, 256>>>(U_re, U_im, W1, b1);
    k_gemv_o<<<EMBED, 256>>>(W2, b2);
    k_broadcast<<<1184, 256>>>((float4*)out);
}